// round 11
// baseline (speedup 1.0000x reference)
#include <cuda_runtime.h>
#include <cuda_bf16.h>
#include <cstdint>

// ---------------------------------------------------------------------------
// Problem constants
// ---------------------------------------------------------------------------
constexpr int H    = 4;
constexpr int C    = 16;
constexpr int DIN  = 128;
constexpr int DOUT = 64;
constexpr int NA   = 150000;
constexpr int NP   = 200000;
constexpr int NOUT = 50000;
constexpr int E    = 1000000;
constexpr int SCB  = (NOUT + 1023) / 1024;   // 49 scan blocks per relation

// ---------------------------------------------------------------------------
// Device scratch (static; no allocations allowed)
// ---------------------------------------------------------------------------
__device__ __align__(16) __nv_bfloat16 g_lb_author[(size_t)NA * DOUT];  // 19.2 MB
__device__ __align__(16) __nv_bfloat16 g_lb_paper [(size_t)NP * DOUT];  // 25.6 MB
__device__ __align__(16) float g_l_paper[(size_t)NOUT * DOUT];          // 12.8 MB (self path, fp32)
__device__ __align__(16) float g_easrc_w [(size_t)NA * H];              // exp(alpha_src)
__device__ __align__(16) float g_easrc_c [(size_t)NP * H];
__device__ int g_cnt [2][NOUT];
__device__ int g_off [2][NOUT + 1];
__device__ int g_cur [2][NOUT];
__device__ int g_csrc[2][E];
__device__ int g_part [2][64];
__device__ int g_pbase[2][64];

// fp32 -> (bf16 hi, bf16 lo residual) packed pairs
__device__ __forceinline__ void split2(float a, float b, uint32_t& hi, uint32_t& lo) {
    __nv_bfloat162 h = __floats2bfloat162_rn(a, b);
    float2 hf = __bfloat1622float2(h);
    __nv_bfloat162 l = __floats2bfloat162_rn(a - hf.x, b - hf.y);
    hi = *(uint32_t*)&h;
    lo = *(uint32_t*)&l;
}

__device__ __forceinline__ void mma16816(float* c, uint32_t a0, uint32_t a1, uint32_t a2,
                                         uint32_t a3, uint32_t b0, uint32_t b1) {
    asm volatile(
        "mma.sync.aligned.m16n8k16.row.col.f32.bf16.bf16.f32 "
        "{%0,%1,%2,%3}, {%4,%5,%6,%7}, {%8,%9}, {%0,%1,%2,%3};"
        : "+f"(c[0]), "+f"(c[1]), "+f"(c[2]), "+f"(c[3])
        : "r"(a0), "r"(a1), "r"(a2), "r"(a3), "r"(b0), "r"(b1));
}

#define LDSM4(r0, r1, r2, r3, addr)                                                  \
    asm volatile("ldmatrix.sync.aligned.m8n8.x4.shared.b16 {%0,%1,%2,%3}, [%4];"     \
        : "=r"(r0), "=r"(r1), "=r"(r2), "=r"(r3) : "r"(addr))

// ---------------------------------------------------------------------------
// K1: bf16-split mma.sync GEMM  l = x @ W + b
//     CTA = 128 rows x 64 cols, 128 threads; warp tile 32x64.
//     Fragments loaded via ldmatrix.x4 (6 LDSM per 16-K step per warp vs 24 LDS).
//     3 passes (hh+hl+lh) -> fp32 acc. Epilogue direct from fragments.
// ---------------------------------------------------------------------------
constexpr int KCH   = 32;
constexpr int APAD  = 40;            // row stride in halfs (80 B = 5*16B: LDSM-aligned) -> banks {0,20,8,28,...}: conflict-free
constexpr int S_AH  = 0;             // 128*80 = 10240
constexpr int S_AL  = 10240;
constexpr int S_WH  = 20480;         // 64*80 = 5120
constexpr int S_WL  = 25600;
constexpr int S_BS  = 30720;         // 64 floats bias
constexpr int S_AT  = 30976;         // 64 floats attn (col-indexed)
constexpr int GSMEM = 31232;

__global__ __launch_bounds__(128, 4) void k_gemm_mma(
    const float* __restrict__ A, int N,
    const float* __restrict__ W, const float* __restrict__ bias,
    const float* __restrict__ attn,
    __nv_bfloat16* __restrict__ outB, float* __restrict__ outF, int nF,
    float* __restrict__ alA)
{
    __shared__ __align__(16) char smem[GSMEM];
    __nv_bfloat16* Ah = (__nv_bfloat16*)(smem + S_AH);
    __nv_bfloat16* Al = (__nv_bfloat16*)(smem + S_AL);
    __nv_bfloat16* Wh = (__nv_bfloat16*)(smem + S_WH);
    __nv_bfloat16* Wl = (__nv_bfloat16*)(smem + S_WL);
    float* bs  = (float*)(smem + S_BS);
    float* as_ = (float*)(smem + S_AT);

    const int tid  = threadIdx.x;
    const int lane = tid & 31;
    const int wp   = tid >> 5;           // 4 warps; warp wp owns rows [wp*32, wp*32+32)
    const int g    = lane >> 2;
    const int q    = lane & 3;
    const int row0 = blockIdx.x * 128;

    if (tid < 64) {
        bs[tid]  = bias[tid];
        as_[tid] = attn[(tid >> 4) * (2 * C) + C + (tid & 15)];
    }

    // LDSM per-lane byte offsets (matrix order chosen so r0..r3 = a0..a3 / b0,b1 pairs)
    // A x4: m0 = rows rb+0..7 @k, m1 = rows rb+8..15 @k, m2 = rows rb+0..7 @k+8, m3 = rows rb+8..15 @k+8
    const uint32_t laneA = (uint32_t)(((lane & 7) + ((lane >> 3) & 1) * 8) * (APAD * 2)
                                      + ((lane >> 4) & 1) * 16);
    // B x4: m0 = n p2*16+0..7 @k, m1 = same n @k+8, m2 = n +8..15 @k, m3 = n +8..15 @k+8
    const uint32_t laneB = (uint32_t)(((lane & 7) + ((lane >> 4) & 1) * 8) * (APAD * 2)
                                      + ((lane >> 3) & 1) * 16);

    const uint32_t sAh = (uint32_t)__cvta_generic_to_shared(Ah);
    const uint32_t sAl = (uint32_t)__cvta_generic_to_shared(Al);
    const uint32_t sWh = (uint32_t)__cvta_generic_to_shared(Wh);
    const uint32_t sWl = (uint32_t)__cvta_generic_to_shared(Wl);

    float acc[2][8][4];
    #pragma unroll
    for (int rt = 0; rt < 2; rt++)
        #pragma unroll
        for (int i = 0; i < 8; i++)
            #pragma unroll
            for (int j = 0; j < 4; j++) acc[rt][i][j] = 0.f;

    for (int c = 0; c < DIN / KCH; c++) {
        const int kc = c * KCH;
        __syncthreads();
        // A chunk: 128 rows x 32 k (8 float4 per thread, coalesced)
        #pragma unroll
        for (int i = 0; i < 8; i++) {
            int idx = i * 128 + tid;
            int r = idx >> 3, kq = idx & 7;
            int gr = row0 + r;
            float4 f = (gr < N) ? *(const float4*)(A + (size_t)gr * DIN + kc + kq * 4)
                                : make_float4(0.f, 0.f, 0.f, 0.f);
            uint32_t h0, l0, h1, l1;
            split2(f.x, f.y, h0, l0);
            split2(f.z, f.w, h1, l1);
            *(uint2*)(Ah + r * APAD + kq * 4) = make_uint2(h0, h1);
            *(uint2*)(Al + r * APAD + kq * 4) = make_uint2(l0, l1);
        }
        // W chunk transposed: Ws[n][k] = W[kc+k][n]
        #pragma unroll
        for (int i = 0; i < 4; i++) {
            int idx = i * 128 + tid;
            int n = idx >> 3, kq = idx & 7;
            float f0 = W[(kc + kq * 4 + 0) * DOUT + n];
            float f1 = W[(kc + kq * 4 + 1) * DOUT + n];
            float f2 = W[(kc + kq * 4 + 2) * DOUT + n];
            float f3 = W[(kc + kq * 4 + 3) * DOUT + n];
            uint32_t h0, l0, h1, l1;
            split2(f0, f1, h0, l0);
            split2(f2, f3, h1, l1);
            *(uint2*)(Wh + n * APAD + kq * 4) = make_uint2(h0, h1);
            *(uint2*)(Wl + n * APAD + kq * 4) = make_uint2(l0, l1);
        }
        __syncthreads();

        const uint32_t Aps[3] = {sAh, sAh, sAl};
        const uint32_t Bps[3] = {sWh, sWl, sWh};
        #pragma unroll
        for (int p = 0; p < 3; p++) {
            const uint32_t baseA = Aps[p] + laneA + wp * 32 * (APAD * 2);
            const uint32_t baseB = Bps[p] + laneB;
            #pragma unroll
            for (int ks = 0; ks < KCH; ks += 16) {
                uint32_t a[2][4];
                LDSM4(a[0][0], a[0][1], a[0][2], a[0][3], baseA + ks * 2);
                LDSM4(a[1][0], a[1][1], a[1][2], a[1][3], baseA + 16 * (APAD * 2) + ks * 2);
                #pragma unroll
                for (int p2 = 0; p2 < 4; p2++) {
                    uint32_t b0A, b1A, b0B, b1B;
                    LDSM4(b0A, b1A, b0B, b1B, baseB + p2 * 16 * (APAD * 2) + ks * 2);
                    mma16816(acc[0][p2 * 2],     a[0][0], a[0][1], a[0][2], a[0][3], b0A, b1A);
                    mma16816(acc[1][p2 * 2],     a[1][0], a[1][1], a[1][2], a[1][3], b0A, b1A);
                    mma16816(acc[0][p2 * 2 + 1], a[0][0], a[0][1], a[0][2], a[0][3], b0B, b1B);
                    mma16816(acc[1][p2 * 2 + 1], a[1][0], a[1][1], a[1][2], a[1][3], b0B, b1B);
                }
            }
        }
    }
    __syncthreads();

    // ---- Epilogue: direct from fragments. Lane owns rows {g, g+8} per rt,
    //      cols {nt*8+q*2, +1}. alpha reduced across the 4 q-lanes via shfl.
    #pragma unroll
    for (int rt = 0; rt < 2; rt++) {
        #pragma unroll
        for (int rh = 0; rh < 2; rh++) {
            int row = wp * 32 + rt * 16 + rh * 8 + g;
            int gr  = row0 + row;
            float ph[4] = {0.f, 0.f, 0.f, 0.f};
            #pragma unroll
            for (int nt = 0; nt < 8; nt++) {
                int col = nt * 8 + q * 2;
                float v0 = acc[rt][nt][rh * 2 + 0] + bs[col];
                float v1 = acc[rt][nt][rh * 2 + 1] + bs[col + 1];
                if (gr < N) {
                    *(__nv_bfloat162*)&outB[(size_t)gr * DOUT + col] =
                        __floats2bfloat162_rn(v0, v1);
                    if (gr < nF)
                        *(float2*)&outF[(size_t)gr * DOUT + col] = make_float2(v0, v1);
                }
                ph[nt >> 1] += fmaxf(v0, 0.2f * v0) * as_[col]
                             + fmaxf(v1, 0.2f * v1) * as_[col + 1];
            }
            #pragma unroll
            for (int hh = 0; hh < 4; hh++) {
                ph[hh] += __shfl_xor_sync(0xffffffffu, ph[hh], 1);
                ph[hh] += __shfl_xor_sync(0xffffffffu, ph[hh], 2);
            }
            if (q == 0 && gr < N)
                *(float4*)&alA[(size_t)gr * H] = make_float4(
                    __expf(ph[0]), __expf(ph[1]), __expf(ph[2]), __expf(ph[3]));
        }
    }
}

// ---------------------------------------------------------------------------
// K0: zero edge counters
// ---------------------------------------------------------------------------
__global__ void k_zero() {
    int i = blockIdx.x * 256 + threadIdx.x;
    if (i < 2 * NOUT) (&g_cnt[0][0])[i] = 0;
}

// ---------------------------------------------------------------------------
// K2: histogram both relations in one pass
// ---------------------------------------------------------------------------
__global__ void k_hist2(const int* __restrict__ d0, const int* __restrict__ d1) {
    int i = blockIdx.x * 256 + threadIdx.x;
    if (i >= E) return;
    atomicAdd(&g_cnt[0][d0[i]], 1);
    atomicAdd(&g_cnt[1][d1[i]], 1);
}

// ---------------------------------------------------------------------------
// K3a/b/c: parallel exclusive scan over counts
// ---------------------------------------------------------------------------
__global__ void k_scanA() {
    __shared__ int ws[32];
    int rel = blockIdx.y;
    int i = blockIdx.x * 1024 + threadIdx.x;
    int v = (i < NOUT) ? g_cnt[rel][i] : 0;
    int lane = threadIdx.x & 31, wid = threadIdx.x >> 5;
    #pragma unroll
    for (int o = 16; o > 0; o >>= 1) v += __shfl_xor_sync(0xffffffffu, v, o);
    if (lane == 0) ws[wid] = v;
    __syncthreads();
    if (wid == 0) {
        int x = ws[lane];
        #pragma unroll
        for (int o = 16; o > 0; o >>= 1) x += __shfl_xor_sync(0xffffffffu, x, o);
        if (lane == 0) g_part[rel][blockIdx.x] = x;
    }
}
__global__ void k_scanB() {
    int rel = threadIdx.x;
    if (rel >= 2) return;
    int run = 0;
    for (int b = 0; b < SCB; b++) { g_pbase[rel][b] = run; run += g_part[rel][b]; }
    g_off[rel][NOUT] = run;
}
__global__ void k_scanC() {
    __shared__ int ws[32];
    int rel = blockIdx.y;
    int i = blockIdx.x * 1024 + threadIdx.x;
    int v = (i < NOUT) ? g_cnt[rel][i] : 0;
    int lane = threadIdx.x & 31, wid = threadIdx.x >> 5;
    int inc = v;
    #pragma unroll
    for (int o = 1; o < 32; o <<= 1) {
        int u = __shfl_up_sync(0xffffffffu, inc, o);
        if (lane >= o) inc += u;
    }
    if (lane == 31) ws[wid] = inc;
    __syncthreads();
    if (wid == 0) {
        int x = ws[lane];
        #pragma unroll
        for (int o = 1; o < 32; o <<= 1) {
            int u = __shfl_up_sync(0xffffffffu, x, o);
            if (lane >= o) x += u;
        }
        ws[lane] = x;
    }
    __syncthreads();
    int excl = inc - v + (wid > 0 ? ws[wid - 1] : 0) + g_pbase[rel][blockIdx.x];
    if (i < NOUT) { g_off[rel][i] = excl; g_cur[rel][i] = excl; }
}

// ---------------------------------------------------------------------------
// K4: scatter both relations into CSR (source index only)
// ---------------------------------------------------------------------------
__global__ void k_scatter2(const int* __restrict__ s0, const int* __restrict__ d0,
                           const int* __restrict__ s1, const int* __restrict__ d1) {
    int i = blockIdx.x * 256 + threadIdx.x;
    if (i >= E) return;
    int p0 = atomicAdd(&g_cur[0][d0[i]], 1);
    g_csrc[0][p0] = s0[i];
    int p1 = atomicAdd(&g_cur[1][d1[i]], 1);
    g_csrc[1][p1] = s1[i];
}

// ---------------------------------------------------------------------------
// K5: fused aggregation (both relations, bf16 feature gathers) + semantic
//     attention. One warp per output node.
// ---------------------------------------------------------------------------
__global__ __launch_bounds__(256) void k_aggfin(
    const float* __restrict__ rel_l, const float* __restrict__ rel_r,
    float* __restrict__ outp)
{
    int n = blockIdx.x * 8 + (threadIdx.x >> 5);
    if (n >= NOUT) return;
    int lane = threadIdx.x & 31;
    int h  = lane >> 3;
    int c0 = lane * 2;
    int ci = c0 & 15;

    float ewx, ewy;
    {
        const int* csrc = g_csrc[0];
        int beg = g_off[0][n], end = g_off[0][n + 1];
        float s = 0.f, a0 = 0.f, a1 = 0.f;
        #pragma unroll 4
        for (int e = beg; e < end; e++) {
            int srci = csrc[e];
            float wg = g_easrc_w[(size_t)srci * H + h];
            float2 xj = __bfloat1622float2(
                *(const __nv_bfloat162*)&g_lb_author[(size_t)srci * DOUT + c0]);
            s  += wg;
            a0 += wg * xj.x;
            a1 += wg * xj.y;
        }
        float inv = 1.f / (s + 1e-16f);
        ewx = a0 * inv; ewy = a1 * inv;
    }
    float ecx, ecy;
    {
        const int* csrc = g_csrc[1];
        int beg = g_off[1][n], end = g_off[1][n + 1];
        float s = 0.f, a0 = 0.f, a1 = 0.f;
        #pragma unroll 4
        for (int e = beg; e < end; e++) {
            int srci = csrc[e];
            float wg = g_easrc_c[(size_t)srci * H + h];
            float2 xj = __bfloat1622float2(
                *(const __nv_bfloat162*)&g_lb_paper[(size_t)srci * DOUT + c0]);
            s  += wg;
            a0 += wg * xj.x;
            a1 += wg * xj.y;
        }
        float inv = 1.f / (s + 1e-16f);
        ecx = a0 * inv; ecy = a1 * inv;
    }

    float2 es = *(const float2*)&g_l_paper[(size_t)n * DOUT + c0];

    float al = es.x * __ldg(&rel_l[h * C + ci]) + es.y * __ldg(&rel_l[h * C + ci + 1]);
    float r0 = ewx * __ldg(&rel_r[0 * H * C + h * C + ci]) + ewy * __ldg(&rel_r[0 * H * C + h * C + ci + 1]);
    float r1 = ecx * __ldg(&rel_r[1 * H * C + h * C + ci]) + ecy * __ldg(&rel_r[1 * H * C + h * C + ci + 1]);
    float r2 = es.x * __ldg(&rel_r[2 * H * C + h * C + ci]) + es.y * __ldg(&rel_r[2 * H * C + h * C + ci + 1]);

    #pragma unroll
    for (int o = 1; o <= 4; o <<= 1) {
        al += __shfl_xor_sync(0xffffffffu, al, o);
        r0 += __shfl_xor_sync(0xffffffffu, r0, o);
        r1 += __shfl_xor_sync(0xffffffffu, r1, o);
        r2 += __shfl_xor_sync(0xffffffffu, r2, o);
    }

    float x0 = al + r0; x0 = fmaxf(x0, 0.2f * x0);
    float x1 = al + r1; x1 = fmaxf(x1, 0.2f * x1);
    float x2 = al + r2; x2 = fmaxf(x2, 0.2f * x2);
    float mx = fmaxf(x0, fmaxf(x1, x2));
    float e0 = __expf(x0 - mx), e1 = __expf(x1 - mx), e2 = __expf(x2 - mx);
    float ib = 1.f / (e0 + e1 + e2);
    float b0 = e0 * ib, b1 = e1 * ib, b2 = e2 * ib;

    float o0 = fmaxf(ewx * b0 + ecx * b1 + es.x * b2, 0.f);
    float o1 = fmaxf(ewy * b0 + ecy * b1 + es.y * b2, 0.f);
    *(float2*)&outp[(size_t)n * DOUT + c0] = make_float2(o0, o1);
}

// ---------------------------------------------------------------------------
// Launch. Slot 4 = gemm(paper): the ncu capture slot.
// ---------------------------------------------------------------------------
extern "C" void kernel_launch(void* const* d_in, const int* in_sizes, int n_in,
                              void* d_out, int out_size) {
    (void)in_sizes; (void)out_size;
    if (n_in < 16) return;
    const float* x_author   = (const float*)d_in[0];
    const float* x_paper    = (const float*)d_in[1];
    const float* W_l_author = (const float*)d_in[2];
    const float* b_l_author = (const float*)d_in[3];
    const float* W_l_paper  = (const float*)d_in[4];
    const float* b_l_paper  = (const float*)d_in[5];
    // d_in[6], d_in[7] (W_r_paper, b_r_paper): softmax-invariant -> unused
    const float* attn_w     = (const float*)d_in[8];
    const float* attn_c     = (const float*)d_in[9];
    const float* rel_l      = (const float*)d_in[10];
    const float* rel_r      = (const float*)d_in[11];
    const int*   src_w      = (const int*)d_in[12];
    const int*   dst_w      = (const int*)d_in[13];
    const int*   src_c      = (const int*)d_in[14];
    const int*   dst_c      = (const int*)d_in[15];
    float* outp = (float*)d_out;

    __nv_bfloat16* lbA; cudaGetSymbolAddress((void**)&lbA, g_lb_author);
    __nv_bfloat16* lbP; cudaGetSymbolAddress((void**)&lbP, g_lb_paper);
    float* lP;  cudaGetSymbolAddress((void**)&lP,  g_l_paper);
    float* eaW; cudaGetSymbolAddress((void**)&eaW, g_easrc_w);
    float* eaC; cudaGetSymbolAddress((void**)&eaC, g_easrc_c);

    k_zero<<<(2 * NOUT + 255) / 256, 256>>>();                                        // 1
    k_hist2<<<(E + 255) / 256, 256>>>(dst_w, dst_c);                                  // 2
    k_gemm_mma<<<(NA + 127) / 128, 128>>>(x_author, NA, W_l_author, b_l_author,
                                          attn_w, lbA, lP, 0, eaW);                   // 3
    k_gemm_mma<<<(NP + 127) / 128, 128>>>(x_paper,  NP, W_l_paper,  b_l_paper,
                                          attn_c, lbP, lP, NOUT, eaC);                // 4 <- profiled
    k_scanA<<<dim3(SCB, 2), 1024>>>();                                                // 5
    k_scanB<<<1, 2>>>();                                                              // 6
    k_scanC<<<dim3(SCB, 2), 1024>>>();                                                // 7
    k_scatter2<<<(E + 255) / 256, 256>>>(src_w, dst_w, src_c, dst_c);                 // 8
    k_aggfin<<<(NOUT + 7) / 8, 256>>>(rel_l, rel_r, outp);                            // 9
}

// round 13
// speedup vs baseline: 1.0451x; 1.0451x over previous
#include <cuda_runtime.h>
#include <cuda_bf16.h>
#include <cstdint>

// ---------------------------------------------------------------------------
// Problem constants
// ---------------------------------------------------------------------------
constexpr int H    = 4;
constexpr int C    = 16;
constexpr int DIN  = 128;
constexpr int DOUT = 64;
constexpr int NA   = 150000;
constexpr int NP   = 200000;
constexpr int NOUT = 50000;
constexpr int E    = 1000000;
constexpr int SCB  = (NOUT + 1023) / 1024;   // 49 scan blocks per relation

// ---------------------------------------------------------------------------
// Device scratch (static; no allocations allowed)
// ---------------------------------------------------------------------------
__device__ __align__(16) __nv_bfloat16 g_lb_author[(size_t)NA * DOUT];  // 19.2 MB
__device__ __align__(16) __nv_bfloat16 g_lb_paper [(size_t)NP * DOUT];  // 25.6 MB
__device__ __align__(16) float g_l_paper[(size_t)NOUT * DOUT];          // 12.8 MB (self path, fp32)
__device__ __align__(16) float g_easrc_w [(size_t)NA * H];              // exp(alpha_src)
__device__ __align__(16) float g_easrc_c [(size_t)NP * H];
__device__ int g_cnt [2][NOUT];
__device__ int g_off [2][NOUT + 1];
__device__ int g_cur [2][NOUT];
__device__ int g_csrc[2][E];
__device__ int g_part [2][64];
__device__ int g_pbase[2][64];

// fp32 -> (bf16 hi, bf16 lo residual) packed pairs
__device__ __forceinline__ void split2(float a, float b, uint32_t& hi, uint32_t& lo) {
    __nv_bfloat162 h = __floats2bfloat162_rn(a, b);
    float2 hf = __bfloat1622float2(h);
    __nv_bfloat162 l = __floats2bfloat162_rn(a - hf.x, b - hf.y);
    hi = *(uint32_t*)&h;
    lo = *(uint32_t*)&l;
}

__device__ __forceinline__ void mma16816(float* c, uint32_t a0, uint32_t a1, uint32_t a2,
                                         uint32_t a3, uint32_t b0, uint32_t b1) {
    asm volatile(
        "mma.sync.aligned.m16n8k16.row.col.f32.bf16.bf16.f32 "
        "{%0,%1,%2,%3}, {%4,%5,%6,%7}, {%8,%9}, {%0,%1,%2,%3};"
        : "+f"(c[0]), "+f"(c[1]), "+f"(c[2]), "+f"(c[3])
        : "r"(a0), "r"(a1), "r"(a2), "r"(a3), "r"(b0), "r"(b1));
}

#define LDSM4(r0, r1, r2, r3, addr)                                                  \
    asm volatile("ldmatrix.sync.aligned.m8n8.x4.shared.b16 {%0,%1,%2,%3}, [%4];"     \
        : "=r"(r0), "=r"(r1), "=r"(r2), "=r"(r3) : "r"(addr))

// ---------------------------------------------------------------------------
// K1: bf16-split mma.sync GEMM  l = x @ W + b
//     CTA = 128 rows x 64 cols, 128 threads; warp tile 32x64.
//     PASS-FUSED inner loop: per 16-K step load Ah/Al once and each Wh/Wl
//     pair once, then issue all hh+hl+lh MMAs from registers.
//     LDS bytes per warp-kstep: 18 -> 12 ldsm.x4 (-33% on the binding resource).
// ---------------------------------------------------------------------------
constexpr int KCH   = 32;
constexpr int APAD  = 40;            // row stride in halfs (80 B = 5*16B) -> LDSM banks conflict-free
constexpr int S_AH  = 0;             // 128*80 = 10240
constexpr int S_AL  = 10240;
constexpr int S_WH  = 20480;         // 64*80 = 5120
constexpr int S_WL  = 25600;
constexpr int S_BS  = 30720;         // 64 floats bias
constexpr int S_AT  = 30976;         // 64 floats attn (col-indexed)
constexpr int GSMEM = 31232;

__global__ __launch_bounds__(128, 4) void k_gemm_mma(
    const float* __restrict__ A, int N,
    const float* __restrict__ W, const float* __restrict__ bias,
    const float* __restrict__ attn,
    __nv_bfloat16* __restrict__ outB, float* __restrict__ outF, int nF,
    float* __restrict__ alA)
{
    __shared__ __align__(16) char smem[GSMEM];
    __nv_bfloat16* Ah = (__nv_bfloat16*)(smem + S_AH);
    __nv_bfloat16* Al = (__nv_bfloat16*)(smem + S_AL);
    __nv_bfloat16* Wh = (__nv_bfloat16*)(smem + S_WH);
    __nv_bfloat16* Wl = (__nv_bfloat16*)(smem + S_WL);
    float* bs  = (float*)(smem + S_BS);
    float* as_ = (float*)(smem + S_AT);

    const int tid  = threadIdx.x;
    const int lane = tid & 31;
    const int wp   = tid >> 5;           // 4 warps; warp wp owns rows [wp*32, wp*32+32)
    const int g    = lane >> 2;
    const int q    = lane & 3;
    const int row0 = blockIdx.x * 128;

    if (tid < 64) {
        bs[tid]  = bias[tid];
        as_[tid] = attn[(tid >> 4) * (2 * C) + C + (tid & 15)];
    }

    // LDSM per-lane byte offsets
    // A x4: m0 = rows rb+0..7 @k, m1 = rows rb+8..15 @k, m2 = rows rb+0..7 @k+8, m3 = rows rb+8..15 @k+8
    const uint32_t laneA = (uint32_t)(((lane & 7) + ((lane >> 3) & 1) * 8) * (APAD * 2)
                                      + ((lane >> 4) & 1) * 16);
    // B x4: m0 = n 0..7 @k, m1 = same n @k+8, m2 = n 8..15 @k, m3 = n 8..15 @k+8
    const uint32_t laneB = (uint32_t)(((lane & 7) + ((lane >> 4) & 1) * 8) * (APAD * 2)
                                      + ((lane >> 3) & 1) * 16);

    const uint32_t sAh = (uint32_t)__cvta_generic_to_shared(Ah);
    const uint32_t sAl = (uint32_t)__cvta_generic_to_shared(Al);
    const uint32_t sWh = (uint32_t)__cvta_generic_to_shared(Wh);
    const uint32_t sWl = (uint32_t)__cvta_generic_to_shared(Wl);

    float acc[2][8][4];
    #pragma unroll
    for (int rt = 0; rt < 2; rt++)
        #pragma unroll
        for (int i = 0; i < 8; i++)
            #pragma unroll
            for (int j = 0; j < 4; j++) acc[rt][i][j] = 0.f;

    for (int c = 0; c < DIN / KCH; c++) {
        const int kc = c * KCH;
        __syncthreads();
        // A chunk: 128 rows x 32 k (8 float4 per thread, coalesced)
        #pragma unroll
        for (int i = 0; i < 8; i++) {
            int idx = i * 128 + tid;
            int r = idx >> 3, kq = idx & 7;
            int gr = row0 + r;
            float4 f = (gr < N) ? *(const float4*)(A + (size_t)gr * DIN + kc + kq * 4)
                                : make_float4(0.f, 0.f, 0.f, 0.f);
            uint32_t h0, l0, h1, l1;
            split2(f.x, f.y, h0, l0);
            split2(f.z, f.w, h1, l1);
            *(uint2*)(Ah + r * APAD + kq * 4) = make_uint2(h0, h1);
            *(uint2*)(Al + r * APAD + kq * 4) = make_uint2(l0, l1);
        }
        // W chunk transposed: Ws[n][k] = W[kc+k][n]
        #pragma unroll
        for (int i = 0; i < 4; i++) {
            int idx = i * 128 + tid;
            int n = idx >> 3, kq = idx & 7;
            float f0 = W[(kc + kq * 4 + 0) * DOUT + n];
            float f1 = W[(kc + kq * 4 + 1) * DOUT + n];
            float f2 = W[(kc + kq * 4 + 2) * DOUT + n];
            float f3 = W[(kc + kq * 4 + 3) * DOUT + n];
            uint32_t h0, l0, h1, l1;
            split2(f0, f1, h0, l0);
            split2(f2, f3, h1, l1);
            *(uint2*)(Wh + n * APAD + kq * 4) = make_uint2(h0, h1);
            *(uint2*)(Wl + n * APAD + kq * 4) = make_uint2(l0, l1);
        }
        __syncthreads();

        const uint32_t baseAh = sAh + laneA + wp * 32 * (APAD * 2);
        const uint32_t baseAl = sAl + laneA + wp * 32 * (APAD * 2);
        const uint32_t baseBh = sWh + laneB;
        const uint32_t baseBl = sWl + laneB;
        #pragma unroll
        for (int ks = 0; ks < KCH; ks += 16) {
            uint32_t ah[2][4], al[2][4];
            LDSM4(ah[0][0], ah[0][1], ah[0][2], ah[0][3], baseAh + ks * 2);
            LDSM4(ah[1][0], ah[1][1], ah[1][2], ah[1][3], baseAh + 16 * (APAD * 2) + ks * 2);
            LDSM4(al[0][0], al[0][1], al[0][2], al[0][3], baseAl + ks * 2);
            LDSM4(al[1][0], al[1][1], al[1][2], al[1][3], baseAl + 16 * (APAD * 2) + ks * 2);
            #pragma unroll
            for (int p2 = 0; p2 < 4; p2++) {
                uint32_t bh0, bh1, bh2, bh3, bl0, bl1, bl2, bl3;
                LDSM4(bh0, bh1, bh2, bh3, baseBh + p2 * 16 * (APAD * 2) + ks * 2);
                LDSM4(bl0, bl1, bl2, bl3, baseBl + p2 * 16 * (APAD * 2) + ks * 2);
                // hh
                mma16816(acc[0][p2 * 2],     ah[0][0], ah[0][1], ah[0][2], ah[0][3], bh0, bh1);
                mma16816(acc[1][p2 * 2],     ah[1][0], ah[1][1], ah[1][2], ah[1][3], bh0, bh1);
                mma16816(acc[0][p2 * 2 + 1], ah[0][0], ah[0][1], ah[0][2], ah[0][3], bh2, bh3);
                mma16816(acc[1][p2 * 2 + 1], ah[1][0], ah[1][1], ah[1][2], ah[1][3], bh2, bh3);
                // hl
                mma16816(acc[0][p2 * 2],     ah[0][0], ah[0][1], ah[0][2], ah[0][3], bl0, bl1);
                mma16816(acc[1][p2 * 2],     ah[1][0], ah[1][1], ah[1][2], ah[1][3], bl0, bl1);
                mma16816(acc[0][p2 * 2 + 1], ah[0][0], ah[0][1], ah[0][2], ah[0][3], bl2, bl3);
                mma16816(acc[1][p2 * 2 + 1], ah[1][0], ah[1][1], ah[1][2], ah[1][3], bl2, bl3);
                // lh
                mma16816(acc[0][p2 * 2],     al[0][0], al[0][1], al[0][2], al[0][3], bh0, bh1);
                mma16816(acc[1][p2 * 2],     al[1][0], al[1][1], al[1][2], al[1][3], bh0, bh1);
                mma16816(acc[0][p2 * 2 + 1], al[0][0], al[0][1], al[0][2], al[0][3], bh2, bh3);
                mma16816(acc[1][p2 * 2 + 1], al[1][0], al[1][1], al[1][2], al[1][3], bh2, bh3);
            }
        }
    }
    __syncthreads();

    // ---- Epilogue: direct from fragments. Lane owns rows {g, g+8} per rt,
    //      cols {nt*8+q*2, +1}. alpha reduced across the 4 q-lanes via shfl.
    #pragma unroll
    for (int rt = 0; rt < 2; rt++) {
        #pragma unroll
        for (int rh = 0; rh < 2; rh++) {
            int row = wp * 32 + rt * 16 + rh * 8 + g;
            int gr  = row0 + row;
            float ph[4] = {0.f, 0.f, 0.f, 0.f};
            #pragma unroll
            for (int nt = 0; nt < 8; nt++) {
                int col = nt * 8 + q * 2;
                float v0 = acc[rt][nt][rh * 2 + 0] + bs[col];
                float v1 = acc[rt][nt][rh * 2 + 1] + bs[col + 1];
                if (gr < N) {
                    *(__nv_bfloat162*)&outB[(size_t)gr * DOUT + col] =
                        __floats2bfloat162_rn(v0, v1);
                    if (gr < nF)
                        *(float2*)&outF[(size_t)gr * DOUT + col] = make_float2(v0, v1);
                }
                ph[nt >> 1] += fmaxf(v0, 0.2f * v0) * as_[col]
                             + fmaxf(v1, 0.2f * v1) * as_[col + 1];
            }
            #pragma unroll
            for (int hh = 0; hh < 4; hh++) {
                ph[hh] += __shfl_xor_sync(0xffffffffu, ph[hh], 1);
                ph[hh] += __shfl_xor_sync(0xffffffffu, ph[hh], 2);
            }
            if (q == 0 && gr < N)
                *(float4*)&alA[(size_t)gr * H] = make_float4(
                    __expf(ph[0]), __expf(ph[1]), __expf(ph[2]), __expf(ph[3]));
        }
    }
}

// ---------------------------------------------------------------------------
// K0: zero edge counters
// ---------------------------------------------------------------------------
__global__ void k_zero() {
    int i = blockIdx.x * 256 + threadIdx.x;
    if (i < 2 * NOUT) (&g_cnt[0][0])[i] = 0;
}

// ---------------------------------------------------------------------------
// K2: histogram both relations in one pass
// ---------------------------------------------------------------------------
__global__ void k_hist2(const int* __restrict__ d0, const int* __restrict__ d1) {
    int i = blockIdx.x * 256 + threadIdx.x;
    if (i >= E) return;
    atomicAdd(&g_cnt[0][d0[i]], 1);
    atomicAdd(&g_cnt[1][d1[i]], 1);
}

// ---------------------------------------------------------------------------
// K3a/b/c: parallel exclusive scan over counts
// ---------------------------------------------------------------------------
__global__ void k_scanA() {
    __shared__ int ws[32];
    int rel = blockIdx.y;
    int i = blockIdx.x * 1024 + threadIdx.x;
    int v = (i < NOUT) ? g_cnt[rel][i] : 0;
    int lane = threadIdx.x & 31, wid = threadIdx.x >> 5;
    #pragma unroll
    for (int o = 16; o > 0; o >>= 1) v += __shfl_xor_sync(0xffffffffu, v, o);
    if (lane == 0) ws[wid] = v;
    __syncthreads();
    if (wid == 0) {
        int x = ws[lane];
        #pragma unroll
        for (int o = 16; o > 0; o >>= 1) x += __shfl_xor_sync(0xffffffffu, x, o);
        if (lane == 0) g_part[rel][blockIdx.x] = x;
    }
}
__global__ void k_scanB() {
    int rel = threadIdx.x;
    if (rel >= 2) return;
    int run = 0;
    for (int b = 0; b < SCB; b++) { g_pbase[rel][b] = run; run += g_part[rel][b]; }
    g_off[rel][NOUT] = run;
}
__global__ void k_scanC() {
    __shared__ int ws[32];
    int rel = blockIdx.y;
    int i = blockIdx.x * 1024 + threadIdx.x;
    int v = (i < NOUT) ? g_cnt[rel][i] : 0;
    int lane = threadIdx.x & 31, wid = threadIdx.x >> 5;
    int inc = v;
    #pragma unroll
    for (int o = 1; o < 32; o <<= 1) {
        int u = __shfl_up_sync(0xffffffffu, inc, o);
        if (lane >= o) inc += u;
    }
    if (lane == 31) ws[wid] = inc;
    __syncthreads();
    if (wid == 0) {
        int x = ws[lane];
        #pragma unroll
        for (int o = 1; o < 32; o <<= 1) {
            int u = __shfl_up_sync(0xffffffffu, x, o);
            if (lane >= o) x += u;
        }
        ws[lane] = x;
    }
    __syncthreads();
    int excl = inc - v + (wid > 0 ? ws[wid - 1] : 0) + g_pbase[rel][blockIdx.x];
    if (i < NOUT) { g_off[rel][i] = excl; g_cur[rel][i] = excl; }
}

// ---------------------------------------------------------------------------
// K4: scatter both relations into CSR (source index only)
// ---------------------------------------------------------------------------
__global__ void k_scatter2(const int* __restrict__ s0, const int* __restrict__ d0,
                           const int* __restrict__ s1, const int* __restrict__ d1) {
    int i = blockIdx.x * 256 + threadIdx.x;
    if (i >= E) return;
    int p0 = atomicAdd(&g_cur[0][d0[i]], 1);
    g_csrc[0][p0] = s0[i];
    int p1 = atomicAdd(&g_cur[1][d1[i]], 1);
    g_csrc[1][p1] = s1[i];
}

// ---------------------------------------------------------------------------
// K5: fused aggregation (both relations, bf16 feature gathers) + semantic
//     attention. One warp per output node.
// ---------------------------------------------------------------------------
__global__ __launch_bounds__(256) void k_aggfin(
    const float* __restrict__ rel_l, const float* __restrict__ rel_r,
    float* __restrict__ outp)
{
    int n = blockIdx.x * 8 + (threadIdx.x >> 5);
    if (n >= NOUT) return;
    int lane = threadIdx.x & 31;
    int h  = lane >> 3;
    int c0 = lane * 2;
    int ci = c0 & 15;

    float ewx, ewy;
    {
        const int* csrc = g_csrc[0];
        int beg = g_off[0][n], end = g_off[0][n + 1];
        float s = 0.f, a0 = 0.f, a1 = 0.f;
        #pragma unroll 4
        for (int e = beg; e < end; e++) {
            int srci = csrc[e];
            float wg = g_easrc_w[(size_t)srci * H + h];
            float2 xj = __bfloat1622float2(
                *(const __nv_bfloat162*)&g_lb_author[(size_t)srci * DOUT + c0]);
            s  += wg;
            a0 += wg * xj.x;
            a1 += wg * xj.y;
        }
        float inv = 1.f / (s + 1e-16f);
        ewx = a0 * inv; ewy = a1 * inv;
    }
    float ecx, ecy;
    {
        const int* csrc = g_csrc[1];
        int beg = g_off[1][n], end = g_off[1][n + 1];
        float s = 0.f, a0 = 0.f, a1 = 0.f;
        #pragma unroll 4
        for (int e = beg; e < end; e++) {
            int srci = csrc[e];
            float wg = g_easrc_c[(size_t)srci * H + h];
            float2 xj = __bfloat1622float2(
                *(const __nv_bfloat162*)&g_lb_paper[(size_t)srci * DOUT + c0]);
            s  += wg;
            a0 += wg * xj.x;
            a1 += wg * xj.y;
        }
        float inv = 1.f / (s + 1e-16f);
        ecx = a0 * inv; ecy = a1 * inv;
    }

    float2 es = *(const float2*)&g_l_paper[(size_t)n * DOUT + c0];

    float al = es.x * __ldg(&rel_l[h * C + ci]) + es.y * __ldg(&rel_l[h * C + ci + 1]);
    float r0 = ewx * __ldg(&rel_r[0 * H * C + h * C + ci]) + ewy * __ldg(&rel_r[0 * H * C + h * C + ci + 1]);
    float r1 = ecx * __ldg(&rel_r[1 * H * C + h * C + ci]) + ecy * __ldg(&rel_r[1 * H * C + h * C + ci + 1]);
    float r2 = es.x * __ldg(&rel_r[2 * H * C + h * C + ci]) + es.y * __ldg(&rel_r[2 * H * C + h * C + ci + 1]);

    #pragma unroll
    for (int o = 1; o <= 4; o <<= 1) {
        al += __shfl_xor_sync(0xffffffffu, al, o);
        r0 += __shfl_xor_sync(0xffffffffu, r0, o);
        r1 += __shfl_xor_sync(0xffffffffu, r1, o);
        r2 += __shfl_xor_sync(0xffffffffu, r2, o);
    }

    float x0 = al + r0; x0 = fmaxf(x0, 0.2f * x0);
    float x1 = al + r1; x1 = fmaxf(x1, 0.2f * x1);
    float x2 = al + r2; x2 = fmaxf(x2, 0.2f * x2);
    float mx = fmaxf(x0, fmaxf(x1, x2));
    float e0 = __expf(x0 - mx), e1 = __expf(x1 - mx), e2 = __expf(x2 - mx);
    float ib = 1.f / (e0 + e1 + e2);
    float b0 = e0 * ib, b1 = e1 * ib, b2 = e2 * ib;

    float o0 = fmaxf(ewx * b0 + ecx * b1 + es.x * b2, 0.f);
    float o1 = fmaxf(ewy * b0 + ecy * b1 + es.y * b2, 0.f);
    *(float2*)&outp[(size_t)n * DOUT + c0] = make_float2(o0, o1);
}

// ---------------------------------------------------------------------------
// Launch. Slot 4 = gemm(paper): the ncu capture slot.
// ---------------------------------------------------------------------------
extern "C" void kernel_launch(void* const* d_in, const int* in_sizes, int n_in,
                              void* d_out, int out_size) {
    (void)in_sizes; (void)out_size;
    if (n_in < 16) return;
    const float* x_author   = (const float*)d_in[0];
    const float* x_paper    = (const float*)d_in[1];
    const float* W_l_author = (const float*)d_in[2];
    const float* b_l_author = (const float*)d_in[3];
    const float* W_l_paper  = (const float*)d_in[4];
    const float* b_l_paper  = (const float*)d_in[5];
    // d_in[6], d_in[7] (W_r_paper, b_r_paper): softmax-invariant -> unused
    const float* attn_w     = (const float*)d_in[8];
    const float* attn_c     = (const float*)d_in[9];
    const float* rel_l      = (const float*)d_in[10];
    const float* rel_r      = (const float*)d_in[11];
    const int*   src_w      = (const int*)d_in[12];
    const int*   dst_w      = (const int*)d_in[13];
    const int*   src_c      = (const int*)d_in[14];
    const int*   dst_c      = (const int*)d_in[15];
    float* outp = (float*)d_out;

    __nv_bfloat16* lbA; cudaGetSymbolAddress((void**)&lbA, g_lb_author);
    __nv_bfloat16* lbP; cudaGetSymbolAddress((void**)&lbP, g_lb_paper);
    float* lP;  cudaGetSymbolAddress((void**)&lP,  g_l_paper);
    float* eaW; cudaGetSymbolAddress((void**)&eaW, g_easrc_w);
    float* eaC; cudaGetSymbolAddress((void**)&eaC, g_easrc_c);

    k_zero<<<(2 * NOUT + 255) / 256, 256>>>();                                        // 1
    k_hist2<<<(E + 255) / 256, 256>>>(dst_w, dst_c);                                  // 2
    k_gemm_mma<<<(NA + 127) / 128, 128>>>(x_author, NA, W_l_author, b_l_author,
                                          attn_w, lbA, lP, 0, eaW);                   // 3
    k_gemm_mma<<<(NP + 127) / 128, 128>>>(x_paper,  NP, W_l_paper,  b_l_paper,
                                          attn_c, lbP, lP, NOUT, eaC);                // 4 <- profiled
    k_scanA<<<dim3(SCB, 2), 1024>>>();                                                // 5
    k_scanB<<<1, 2>>>();                                                              // 6
    k_scanC<<<dim3(SCB, 2), 1024>>>();                                                // 7
    k_scatter2<<<(E + 255) / 256, 256>>>(src_w, dst_w, src_c, dst_c);                 // 8
    k_aggfin<<<(NOUT + 7) / 8, 256>>>(rel_l, rel_r, outp);                            // 9
}